// round 17
// baseline (speedup 1.0000x reference)
#include <cuda_runtime.h>
#include <math.h>
#include <float.h>

// Problem dims
#define NV 32000
#define ND 256
#define NH 512
#define NB 16
#define NS 400
#define NT 100
#define NEX 50
#define NVX 32050   // NV + NEX
#define G4 2048     // 4*NH
#define NBLK 128    // persistent-kernel grid
#define HPAD 516    // 512+4 conflict-free float4 stride

// megadec smem layout (floats)
#define SMSZ 12256          // 49,024 bytes
#define SM_LOGIT 4096       // vocab: exp'd logits [half*4000 + b*250 + tid], 8000
#define SM_PS 12096         // vocab: per-warp partial sums, 128
#define SM_RED 12224        // reductions / S+scale, 32

// ---------------- scratch ----------------
__device__ float dEncWT_f[768 * G4];
__device__ float dEncWT_b[768 * G4];
__device__ float dDecWT[1024 * G4];
__device__ float dWprojT[1024 * NH];
__device__ float dW2hT[1024 * NH];
__device__ float dW2cT[1024 * NH];
__device__ float dWo1T[1024 * NH];
__device__ float dWo2T[NH * ND];
__device__ float dEmbT[ND * NV];

__device__ float d_gx[2 * NB * NS * G4];

__device__ float d_hf[2 * NB * NH];
__device__ float d_hb[2 * NB * NH];
__device__ float d_cf[NB * NH], d_cb[NB * NH];
__device__ float d_ys[NB * NS * 1024];
__device__ float d_enc[NB * NS * NH];
__device__ float d_dh[2 * NB * NH];
__device__ float d_dc[2 * NB * NH];
__device__ float d_ctx[NB * NH];
__device__ float d_attn[NB * NS];
__device__ float d_scores[NB * NS];
__device__ float d_pgen2[2 * NB];        // ping-pong pgen
__device__ float d_tmp1[NB * NH];
__device__ float d_dout2[2 * NB * ND];   // ping-pong dec_out (buf1 = init)
__device__ float d_seqmean[NB * NH];
__device__ float d_pgp[NB * 4];          // pgen partials (4 j-slices of 128)
__device__ float d_ps6[64 * NB];         // per-vocab-block exp-sums

// ---------------- hierarchical barrier ----------------
__device__ unsigned int g_cnt[3][8];
__device__ unsigned int g_done[3];
__device__ volatile unsigned int g_gen2[3];

__device__ __forceinline__ void abarrier2(int id, int sub, unsigned int subTarget) {
    __syncthreads();
    if (threadIdx.x == 0) {
        __threadfence();
        unsigned int gen = g_gen2[id];
        bool released = false;
        if (atomicAdd(&g_cnt[id][sub], 1u) == subTarget - 1u) {
            if (atomicAdd(&g_done[id], 1u) == 7u) {
                g_done[id] = 0;
#pragma unroll
                for (int i = 0; i < 8; i++) g_cnt[id][i] = 0;
                __threadfence();
                g_gen2[id] = gen + 1u;
                released = true;
            }
        }
        if (!released) {
            while (g_gen2[id] == gen) { __nanosleep(32); }
        }
        __threadfence();
    }
    __syncthreads();
}

// ---------------- fast math ----------------
__device__ __forceinline__ float fexp(float x) { return __expf(x); }
__device__ __forceinline__ float flog(float x) { return __logf(x); }
__device__ __forceinline__ float sigf(float x) {
    return __fdividef(1.0f, 1.0f + __expf(-x));
}
__device__ __forceinline__ float ftanh(float x) {
    float e = __expf(2.0f * x);
    return (e - 1.0f) * __fdividef(1.0f, e + 1.0f);
}

__device__ __forceinline__ float warpReduceSum(float v) {
#pragma unroll
    for (int o = 16; o > 0; o >>= 1) v += __shfl_xor_sync(0xffffffffu, v, o);
    return v;
}
__device__ __forceinline__ float warpReduceMax(float v) {
#pragma unroll
    for (int o = 16; o > 0; o >>= 1) v = fmaxf(v, __shfl_xor_sync(0xffffffffu, v, o));
    return v;
}
__device__ float blockReduceSum(float v, float* red) {
    int lane = threadIdx.x & 31, w = threadIdx.x >> 5, nw = blockDim.x >> 5;
    v = warpReduceSum(v);
    if (lane == 0) red[w] = v;
    __syncthreads();
    float r = (threadIdx.x < nw) ? red[threadIdx.x] : 0.0f;
    if (w == 0) r = warpReduceSum(r);
    if (threadIdx.x == 0) red[0] = r;
    __syncthreads();
    float res = red[0];
    __syncthreads();
    return res;
}
__device__ float blockReduceMax(float v, float* red) {
    int lane = threadIdx.x & 31, w = threadIdx.x >> 5, nw = blockDim.x >> 5;
    v = warpReduceMax(v);
    if (lane == 0) red[w] = v;
    __syncthreads();
    float r = (threadIdx.x < nw) ? red[threadIdx.x] : -FLT_MAX;
    if (w == 0) r = warpReduceMax(r);
    if (threadIdx.x == 0) red[0] = r;
    __syncthreads();
    float res = red[0];
    __syncthreads();
    return res;
}

// ---------------- transpose tile ----------------
__device__ __forceinline__ void transpose_tile(const float* __restrict__ src, int M, int N,
                                               float* __restrict__ dst, int rowOff, int stride,
                                               float (*tile)[33], int bx, int by) {
    if (bx * 32 >= N || by * 32 >= M) return;
    int tx = threadIdx.x, ty = threadIdx.y;
#pragma unroll
    for (int j = 0; j < 32; j += 8) {
        int n = bx * 32 + tx;
        int m = by * 32 + ty + j;
        if (n < N && m < M) tile[ty + j][tx] = src[(size_t)m * N + n];
    }
    __syncthreads();
#pragma unroll
    for (int j = 0; j < 32; j += 8) {
        int m2 = by * 32 + tx;
        int n2 = bx * 32 + ty + j;
        if (n2 < N && m2 < M) dst[(size_t)(rowOff + n2) * stride + m2] = tile[tx][ty + j];
    }
}

// launch 0: all weight transposes
__global__ void k_setup_w(const float* eWih_f, const float* eWhh_f,
                          const float* eWih_b, const float* eWhh_b,
                          const float* dWih, const float* dWhh,
                          const float* Wproj, const float* W2h,
                          const float* W2c, const float* Wo1, const float* Wo2) {
    __shared__ float tile[32][33];
    int bx = blockIdx.x, by = blockIdx.y;
    switch (blockIdx.z) {
        case 0:  transpose_tile(eWih_f, 2048, 256, dEncWT_f, 0,   G4, tile, bx, by); break;
        case 1:  transpose_tile(eWhh_f, 2048, 512, dEncWT_f, 256, G4, tile, bx, by); break;
        case 2:  transpose_tile(eWih_b, 2048, 256, dEncWT_b, 0,   G4, tile, bx, by); break;
        case 3:  transpose_tile(eWhh_b, 2048, 512, dEncWT_b, 256, G4, tile, bx, by); break;
        case 4:  transpose_tile(dWih,   2048, 512, dDecWT,   0,   G4, tile, bx, by); break;
        case 5:  transpose_tile(dWhh,   2048, 512, dDecWT,   512, G4, tile, bx, by); break;
        case 6:  transpose_tile(Wproj,  512, 1024, dWprojT,  0,   NH, tile, bx, by); break;
        case 7:  transpose_tile(W2h,    512, 1024, dW2hT,    0,   NH, tile, bx, by); break;
        case 8:  transpose_tile(W2c,    512, 1024, dW2cT,    0,   NH, tile, bx, by); break;
        case 9:  transpose_tile(Wo1,    512, 1024, dWo1T,    0,   NH, tile, bx, by); break;
        default: transpose_tile(Wo2,    256, 512,  dWo2T,    0,   ND, tile, bx, by); break;
    }
}

// launch 1: gx GEMM (z=0,1) + emb transpose (z=2); grid (32, 250, 3)
__global__ void k_gx_emb(const int* __restrict__ source, const float* __restrict__ emb) {
    if (blockIdx.z == 2) {
        __shared__ float tile[32][33];
        int flat = blockIdx.x + blockIdx.y * 32;
        if (flat >= 8 * 1000) return;
        transpose_tile(emb, NV, ND, dEmbT, 0, NV, tile, flat & 7, flat >> 3);
        return;
    }
    if (blockIdx.y >= 100) return;
    __shared__ float As[16][64];
    __shared__ float Bs[16][64];
    int dir = blockIdx.z;
    const float* W = dir ? dEncWT_b : dEncWT_f;
    int tid = threadIdx.x + threadIdx.y * 32;
    int row0 = blockIdx.y * 64;
    int col0 = blockIdx.x * 64;
    int ty = tid >> 4, tx = tid & 15;
    float acc[4][4];
#pragma unroll
    for (int i = 0; i < 4; i++)
#pragma unroll
        for (int j = 0; j < 4; j++) acc[i][j] = 0.0f;

    int aRow = tid >> 2;
    int aK = (tid & 3) * 4;
    int row = row0 + aRow;
    int b = row / NS, s = row - b * NS;
    int tok = source[b * NS + s];
    for (int k0 = 0; k0 < ND; k0 += 16) {
        const float4 av = *reinterpret_cast<const float4*>(&emb[(size_t)tok * ND + k0 + aK]);
        As[aK + 0][aRow] = av.x;
        As[aK + 1][aRow] = av.y;
        As[aK + 2][aRow] = av.z;
        As[aK + 3][aRow] = av.w;
#pragma unroll
        for (int i = 0; i < 4; i++) {
            int idx = tid + i * 256;
            int r = idx >> 6, c = idx & 63;
            Bs[r][c] = W[(size_t)(k0 + r) * G4 + col0 + c];
        }
        __syncthreads();
#pragma unroll
        for (int kk = 0; kk < 16; kk++) {
            float4 ar = *reinterpret_cast<const float4*>(&As[kk][ty * 4]);
            float4 br = *reinterpret_cast<const float4*>(&Bs[kk][tx * 4]);
            float a[4] = {ar.x, ar.y, ar.z, ar.w};
            float bv[4] = {br.x, br.y, br.z, br.w};
#pragma unroll
            for (int i = 0; i < 4; i++)
#pragma unroll
                for (int j = 0; j < 4; j++) acc[i][j] += a[i] * bv[j];
        }
        __syncthreads();
    }
#pragma unroll
    for (int i = 0; i < 4; i++) {
        int r = row0 + ty * 4 + i;
#pragma unroll
        for (int j = 0; j < 4; j++) {
            int c = col0 + tx * 4 + j;
            d_gx[((size_t)dir * NB * NS + r) * G4 + c] = acc[i][j];
        }
    }
}

// launch 2: persistent encoder (unchanged from R16 winner)
__global__ __launch_bounds__(256) void k_encoder(const int* __restrict__ slen,
                                                 const float* __restrict__ bf,
                                                 const float* __restrict__ bb) {
    __shared__ float hsm[16 * HPAD];
    __shared__ float gsm[512];
    const int tid = threadIdx.x, bid = blockIdx.x;
    const int dir = bid >> 6;
    const int lid = bid & 63;
    const int sub = lid & 7;
    const int j0 = lid << 3;
    float* hglob = dir ? d_hb : d_hf;
    const float* Wp = dir ? dEncWT_b : dEncWT_f;
    const float* bias = dir ? bb : bf;

    hglob[lid * 256 + tid] = 0.0f;

    const int w = tid >> 5, l = tid & 31;
    const int gq = l >> 3, jq = l & 7;
    const int colW = gq * NH + j0 + jq;
    const int j2 = tid >> 4, b2 = tid & 15;
    float creg = 0.0f;
    const int mylen = (tid < 128) ? slen[b2] : 0;
    const float* Wbase = Wp + (size_t)(256 + w * 64) * G4 + colW;

    const int bq0 = tid >> 5, cq0 = tid & 31;
    const int colg0 = (cq0 >> 3) * NH + j0 + (cq0 & 7);
    const float* gxbase = d_gx + (size_t)dir * NB * NS * G4;
    const float biasg = bias[colg0];

    abarrier2(dir, sub, 8);

    for (int t = 0; t < NS; t++) {
        const int pos = dir ? (NS - 1 - t) : t;
        const int pbuf = (t & 1) * NB * NH;

        float gx0 = gxbase[((size_t)bq0 * NS + pos) * G4 + colg0];
        float gx1 = gxbase[((size_t)(bq0 + 8) * NS + pos) * G4 + colg0];

        {
            const float4* hg4 = reinterpret_cast<const float4*>(hglob + pbuf);
            for (int i = tid; i < NB * NH / 4; i += 256) {
                int b = i >> 7, k4 = i & 127;
                reinterpret_cast<float4*>(&hsm[b * HPAD])[k4] = hg4[b * 128 + k4];
            }
        }
        __syncthreads();

        float acc[16];
#pragma unroll
        for (int b = 0; b < 16; b++) acc[b] = 0.0f;
#pragma unroll 4
        for (int k4 = 0; k4 < 16; k4++) {
            int kk = w * 64 + k4 * 4;
            float w0 = Wbase[(size_t)(k4 * 4 + 0) * G4];
            float w1 = Wbase[(size_t)(k4 * 4 + 1) * G4];
            float w2 = Wbase[(size_t)(k4 * 4 + 2) * G4];
            float w3 = Wbase[(size_t)(k4 * 4 + 3) * G4];
#pragma unroll
            for (int b = 0; b < 16; b++) {
                float4 x = *reinterpret_cast<const float4*>(&hsm[b * HPAD + kk]);
                acc[b] += w0 * x.x + w1 * x.y + w2 * x.z + w3 * x.w;
            }
        }
        __syncthreads();
        float hold = (tid < 128) ? hsm[b2 * HPAD + j0 + j2] : 0.0f;
        __syncthreads();
        float* psm = hsm;
#pragma unroll
        for (int b = 0; b < 16; b++) psm[w * 512 + b * 32 + l] = acc[b];
        __syncthreads();

        {
            float s0 = 0.0f, s1 = 0.0f;
#pragma unroll
            for (int w2 = 0; w2 < 8; w2++) {
                s0 += psm[w2 * 512 + bq0 * 32 + cq0];
                s1 += psm[w2 * 512 + (bq0 + 8) * 32 + cq0];
            }
            int gg = cq0 >> 3, jj = cq0 & 7;
            gsm[gg * 128 + jj * 16 + bq0] = s0 + biasg + gx0;
            gsm[gg * 128 + jj * 16 + bq0 + 8] = s1 + biasg + gx1;
        }
        __syncthreads();

        if (tid < 128) {
            float iv = gsm[0 + j2 * 16 + b2];
            float fv = gsm[128 + j2 * 16 + b2];
            float gg = gsm[256 + j2 * 16 + b2];
            float ov = gsm[384 + j2 * 16 + b2];
            float cn = sigf(fv) * creg + sigf(iv) * ftanh(gg);
            float hn = sigf(ov) * ftanh(cn);
            int m = pos < mylen;
            creg = m ? cn : creg;
            hglob[(pbuf ^ (NB * NH)) + b2 * NH + j0 + j2] = m ? hn : hold;
            d_ys[((size_t)b2 * NS + pos) * 1024 + dir * NH + j0 + j2] = m ? hn : 0.0f;
            if (t == NS - 1) {
                float* cg = dir ? d_cb : d_cf;
                cg[b2 * NH + j0 + j2] = creg;
            }
        }
        abarrier2(dir, sub, 8);
    }
}

// launch 3: zero + proj + decinit + software-pipelined decoder
// (chain on blocks 0..63, vocab on blocks 64..127, 5 barrier slots/step)
__global__ __launch_bounds__(256) void k_megadec(
    const int* __restrict__ target, const int* __restrict__ srcext,
    const int* __restrict__ slen, const float* __restrict__ emb,
    const float* __restrict__ bproj,
    const float* __restrict__ b2h, const float* __restrict__ b2c,
    const float* __restrict__ decb, const float* __restrict__ bo1v,
    const float* __restrict__ Wpgen, const float* __restrict__ bpgen,
    float* __restrict__ out)
{
    __shared__ float SM[SMSZ];
    const int tid = threadIdx.x, bid = blockIdx.x;
    const int lane = tid & 31, warp = tid >> 5;
    const int sub = bid & 7;
    float* red = &SM[SM_RED];

    // ---- stage A0: pre-zero entire output once ----
    {
        float4 z4 = make_float4(0.0f, 0.0f, 0.0f, 0.0f);
        float4* o4 = reinterpret_cast<float4*>(out);
        const size_t n4 = (size_t)NT * NB * NVX / 4;
        for (size_t i = (size_t)bid * 256 + tid; i < n4; i += (size_t)NBLK * 256)
            o4[i] = z4;
    }

    // ---- stage A: projection GEMM (800 tiles over 128 blocks) ----
    {
        float* As = SM;
        float* Bs = SM + 1024;
        int ty = tid >> 4, tx = tid & 15;
        int aRow = tid >> 2;
        int aK = (tid & 3) * 4;
        for (int tile = bid; tile < 800; tile += NBLK) {
            int row0 = (tile >> 3) * 64;
            int col0 = (tile & 7) * 64;
            float acc[4][4];
#pragma unroll
            for (int i = 0; i < 4; i++)
#pragma unroll
                for (int j = 0; j < 4; j++) acc[i][j] = 0.0f;
            for (int k0 = 0; k0 < 1024; k0 += 16) {
                const float4 av = *reinterpret_cast<const float4*>(
                    &d_ys[(size_t)(row0 + aRow) * 1024 + k0 + aK]);
                As[(aK + 0) * 64 + aRow] = av.x;
                As[(aK + 1) * 64 + aRow] = av.y;
                As[(aK + 2) * 64 + aRow] = av.z;
                As[(aK + 3) * 64 + aRow] = av.w;
#pragma unroll
                for (int i = 0; i < 4; i++) {
                    int idx = tid + i * 256;
                    int r = idx >> 6, c = idx & 63;
                    Bs[r * 64 + c] = dWprojT[(size_t)(k0 + r) * NH + col0 + c];
                }
                __syncthreads();
#pragma unroll
                for (int kk = 0; kk < 16; kk++) {
                    float4 ar = *reinterpret_cast<const float4*>(&As[kk * 64 + ty * 4]);
                    float4 br = *reinterpret_cast<const float4*>(&Bs[kk * 64 + tx * 4]);
                    float a[4] = {ar.x, ar.y, ar.z, ar.w};
                    float bv[4] = {br.x, br.y, br.z, br.w};
#pragma unroll
                    for (int i = 0; i < 4; i++)
#pragma unroll
                        for (int j = 0; j < 4; j++) acc[i][j] += a[i] * bv[j];
                }
                __syncthreads();
            }
#pragma unroll
            for (int i = 0; i < 4; i++) {
                int r = row0 + ty * 4 + i;
#pragma unroll
                for (int j = 0; j < 4; j++) {
                    int c = col0 + tx * 4 + j;
                    d_enc[(size_t)r * NH + c] = acc[i][j] + bproj[c];
                }
            }
        }
    }
    abarrier2(2, sub, 16);

    // ---- stage B: decoder init ----
    if (bid < 32) {
        int idx = bid * 256 + tid;
        int b = idx >> 9, j = idx & 511;
        float ah = 0.0f, ac = 0.0f;
#pragma unroll 4
        for (int k = 0; k < NH; k++) {
            float hf = d_hf[b * NH + k], hbv = d_hb[b * NH + k];
            float cf = d_cf[b * NH + k], cbv = d_cb[b * NH + k];
            ah += hf * dW2hT[(size_t)k * NH + j] + hbv * dW2hT[(size_t)(k + NH) * NH + j];
            ac += cf * dW2cT[(size_t)k * NH + j] + cbv * dW2cT[(size_t)(k + NH) * NH + j];
        }
        d_dh[idx] = ah + b2h[j];
        d_dc[idx] = ac + b2c[j];
        int len = slen[b];
        float s = 0.0f;
        for (int ss = 0; ss < len; ss++) s += d_enc[((size_t)b * NS + ss) * NH + j];
        d_seqmean[idx] = __fdividef(s, (float)len);
    }
    abarrier2(2, sub, 16);
    if (bid < 32) {
        int idx = bid * 256 + tid;
        int b = idx >> 9, j = idx & 511;
        float a = 0.0f;
#pragma unroll 4
        for (int k = 0; k < NH; k++) {
            a += d_dh[b * NH + k] * dWo1T[(size_t)k * NH + j];
            a += d_seqmean[b * NH + k] * dWo1T[(size_t)(k + NH) * NH + j];
        }
        d_tmp1[idx] = ftanh(a + bo1v[j]);
    }
    abarrier2(2, sub, 16);
    if (bid < 16) {
        int idx = bid * 256 + tid;
        int b = idx >> 8, j = idx & 255;
        float a = 0.0f;
#pragma unroll 4
        for (int k = 0; k < NH; k++) a += d_tmp1[b * NH + k] * dWo2T[(size_t)k * ND + j];
        d_dout2[NB * ND + idx] = a;   // buffer 1 = dec_out(-1)
    }
    abarrier2(2, sub, 16);

    const bool isChain = (bid < 64);
    const int vb = bid - 64;   // vocab block id 0..63

    // chain P1 constants: 2 bgroups x 32 j-slices (16 cols)
    const int bg = bid >> 5, j0q = (bid & 31) << 4;
    const int cA = lane, cB = lane + 32;
    const int colA = (cA >> 4) * NH + j0q + (cA & 15);
    const int colB = (cB >> 4) * NH + j0q + (cB & 15);
    const float* WA = dDecWT + (size_t)(warp * 128) * G4 + colA;
    const float* WB = dDecWT + (size_t)(warp * 128) * G4 + colB;

    // ---- stage C: pipelined loop (t = chain step; tv = t-1 = vocab step) ----
    for (int t = 0; t <= NT; t++) {
        const bool doC = (t < NT) && isChain;
        const bool doV = (t >= 1) && !isChain;
        const int tv = t - 1;
        const int pcur = (t & 1) * NB * NH;
        const int pnxt = ((t + 1) & 1) * NB * NH;
        const float* douts_in = d_dout2 + ((t + 1) & 1) * NB * ND;   // dec_out(t-1)
        float* douts_out = d_dout2 + (t & 1) * NB * ND;              // dec_out(t)
        float* out_t = out + (size_t)t * NB * NVX;
        float* out_tv = out + (size_t)tv * NB * NVX;
        const float* douts_v = d_dout2 + (tv & 1) * NB * ND;

        // ===== slot 1: chain P1 (gates+cell) | vocab P6a =====
        if (doC) {
            for (int idx = tid; idx < 8 * 1024; idx += 256) {
                int bb = idx >> 10, k = idx & 1023;
                int b = bg * 8 + bb;
                float v;
                if (k < ND) v = emb[(size_t)target[b * NT + t] * ND + k];
                else if (k < 2 * ND) v = douts_in[b * ND + k - ND];
                else v = d_dh[pcur + b * NH + k - 2 * ND];
                SM[bb * 1028 + k] = v;
            }
            __syncthreads();
            float accA[8], accB[8];
#pragma unroll
            for (int bb = 0; bb < 8; bb++) { accA[bb] = 0.0f; accB[bb] = 0.0f; }
#pragma unroll 2
            for (int k4 = 0; k4 < 32; k4++) {
                int kk = warp * 128 + k4 * 4;
                float a0 = WA[(size_t)(k4 * 4 + 0) * G4];
                float a1 = WA[(size_t)(k4 * 4 + 1) * G4];
                float a2 = WA[(size_t)(k4 * 4 + 2) * G4];
                float a3 = WA[(size_t)(k4 * 4 + 3) * G4];
                float b0 = WB[(size_t)(k4 * 4 + 0) * G4];
                float b1 = WB[(size_t)(k4 * 4 + 1) * G4];
                float b2v = WB[(size_t)(k4 * 4 + 2) * G4];
                float b3 = WB[(size_t)(k4 * 4 + 3) * G4];
#pragma unroll
                for (int bb = 0; bb < 8; bb++) {
                    float4 x = *reinterpret_cast<const float4*>(&SM[bb * 1028 + kk]);
                    accA[bb] += a0 * x.x + a1 * x.y + a2 * x.z + a3 * x.w;
                    accB[bb] += b0 * x.x + b1 * x.y + b2v * x.z + b3 * x.w;
                }
            }
            __syncthreads();
            // partials: [w][bb][c]  (overwrites staging; reads done)
#pragma unroll
            for (int bb = 0; bb < 8; bb++) {
                SM[warp * 512 + bb * 64 + cA] = accA[bb];
                SM[warp * 512 + bb * 64 + cB] = accB[bb];
            }
            __syncthreads();
            // reduce 512 outs -> gg at SM[4096..4608)
#pragma unroll
            for (int h = 0; h < 2; h++) {
                int idx = h * 256 + tid;
                int bb = idx >> 6, c = idx & 63;
                float s = 0.0f;
#pragma unroll
                for (int w2 = 0; w2 < 8; w2++) s += SM[w2 * 512 + bb * 64 + c];
                int col = (c >> 4) * NH + j0q + (c & 15);
                SM[4096 + idx] = s + decb[col];
            }
            __syncthreads();
            if (tid < 128) {
                int bb = tid >> 4, j2 = tid & 15;
                int b = bg * 8 + bb, jj = j0q + j2;
                float iv = SM[4096 + bb * 64 + 0  + j2];
                float fv = SM[4096 + bb * 64 + 16 + j2];
                float gv = SM[4096 + bb * 64 + 32 + j2];
                float ov = SM[4096 + bb * 64 + 48 + j2];
                float c = d_dc[pcur + b * NH + jj];
                float cn = sigf(fv) * c + sigf(iv) * ftanh(gv);
                float hn = sigf(ov) * ftanh(cn);
                d_dc[pnxt + b * NH + jj] = cn;
                d_dh[pnxt + b * NH + jj] = hn;
            }
        } else if (doV) {
            // P6a: stage dout(tv) + logits/exp cols [vb*500, vb*500+250)
            for (int i = tid; i < NB * ND; i += 256) SM[i] = douts_v[i];
            __syncthreads();
            float pv[NB];
#pragma unroll
            for (int b = 0; b < NB; b++) pv[b] = 0.0f;
            if (tid < 250) {
                int v = vb * 500 + tid;
                float acc[NB];
#pragma unroll
                for (int b = 0; b < NB; b++) acc[b] = 0.0f;
                for (int k = 0; k < ND; k += 4) {
                    float e0 = dEmbT[(size_t)(k + 0) * NV + v];
                    float e1 = dEmbT[(size_t)(k + 1) * NV + v];
                    float e2 = dEmbT[(size_t)(k + 2) * NV + v];
                    float e3 = dEmbT[(size_t)(k + 3) * NV + v];
#pragma unroll
                    for (int b = 0; b < NB; b++) {
                        const float4 dd = *reinterpret_cast<const float4*>(&SM[b * ND + k]);
                        acc[b] += e0 * dd.x + e1 * dd.y + e2 * dd.z + e3 * dd.w;
                    }
                }
#pragma unroll
                for (int b = 0; b < NB; b++) {
                    float p = fexp(acc[b]);
                    pv[b] = p;
                    SM[SM_LOGIT + b * 250 + tid] = p;
                }
            }
#pragma unroll
            for (int b = 0; b < NB; b++) {
                float s = warpReduceSum(pv[b]);
                if (lane == 0) SM[SM_PS + warp * 16 + b] = s;
            }
        }
        abarrier2(2, sub, 16);

        // ===== slot 2: chain P2 (scores) | vocab P6b =====
        if (doC) {
            int b = bid >> 2, s0 = (bid & 3) * 100;
            for (int i = tid; i < NH; i += 256) SM[i] = d_dh[pnxt + b * NH + i];
            __syncthreads();
            int len = slen[b];
            for (int s = s0 + warp; s < s0 + 100; s += 8) {
                const float* er = &d_enc[((size_t)b * NS + s) * NH];
                float p = 0.0f;
#pragma unroll 4
                for (int k = lane; k < NH; k += 32) p += SM[k] * er[k];
                p = warpReduceSum(p);
                if (lane == 0) d_scores[b * NS + s] = (s < len) ? p : -3.402823466e38f;
            }
        } else if (doV) {
            // P6b: cols [vb*500+250, vb*500+500); staging SM[0,4096) persists
            float pv[NB];
#pragma unroll
            for (int b = 0; b < NB; b++) pv[b] = 0.0f;
            if (tid < 250) {
                int v = vb * 500 + 250 + tid;
                float acc[NB];
#pragma unroll
                for (int b = 0; b < NB; b++) acc[b] = 0.0f;
                for (int k = 0; k < ND; k += 4) {
                    float e0 = dEmbT[(size_t)(k + 0) * NV + v];
                    float e1 = dEmbT[(size_t)(k + 1) * NV + v];
                    float e2 = dEmbT[(size_t)(k + 2) * NV + v];
                    float e3 = dEmbT[(size_t)(k + 3) * NV + v];
#pragma unroll
                    for (int b = 0; b < NB; b++) {
                        const float4 dd = *reinterpret_cast<const float4*>(&SM[b * ND + k]);
                        acc[b] += e0 * dd.x + e1 * dd.y + e2 * dd.z + e3 * dd.w;
                    }
                }
#pragma unroll
                for (int b = 0; b < NB; b++) {
                    float p = fexp(acc[b]);
                    pv[b] = p;
                    SM[SM_LOGIT + 4000 + b * 250 + tid] = p;
                }
            }
#pragma unroll
            for (int b = 0; b < NB; b++) {
                float s = warpReduceSum(pv[b]);
                if (lane == 0) SM[SM_PS + warp * 16 + b] += s;
            }
            __syncthreads();
            if (tid < 16) {
                float s = 0.0f;
#pragma unroll
                for (int w2 = 0; w2 < 8; w2++) s += SM[SM_PS + w2 * 16 + tid];
                d_ps6[vb * 16 + tid] = s;
            }
        }
        abarrier2(2, sub, 16);

        // ===== slot 3: chain P3 (softmax+ctx+pgen partials) | vocab P7a =====
        if (doC) {
            int b = bid >> 2, q4 = bid & 3, jsl = q4 * 128;
            for (int s = tid; s < NS; s += 256) SM[s] = d_scores[b * NS + s];
            __syncthreads();
            float m = -FLT_MAX;
            for (int s = tid; s < NS; s += 256) m = fmaxf(m, SM[s]);
            float M = blockReduceMax(m, red);
            float su = 0.0f;
            for (int s = tid; s < NS; s += 256) {
                float e = fexp(SM[s] - M);
                SM[s] = e;
                su += e;
            }
            float S = blockReduceSum(su, red);
            float inv = __fdividef(1.0f, S);
            if (q4 == 0) {
                for (int s = tid; s < NS; s += 256) d_attn[b * NS + s] = SM[s] * inv;
            }
            __syncthreads();
            {
                int q = tid >> 7, j = tid & 127;
                int jg = jsl + j;
                const float* eb = &d_enc[(size_t)b * NS * NH + jg];
                float a = 0.0f;
#pragma unroll 8
                for (int s = q; s < NS; s += 2)
                    a += SM[s] * eb[(size_t)s * NH];
                SM[512 + tid] = a;
            }
            __syncthreads();
            if (tid < 128) {
                float c = (SM[512 + tid] + SM[640 + tid]) * inv;
                SM[768 + tid] = c;
                d_ctx[b * NH + jsl + tid] = c;
            }
            __syncthreads();
            float pp = 0.0f;
            if (tid < 128) pp = Wpgen[jsl + tid] * SM[768 + tid];
            if (q4 == 1) {
                int tok = target[b * NT + t];
                for (int k = tid; k < 1024; k += 256) {
                    float cv;
                    if (k < NH) cv = d_dh[pnxt + b * NH + k];
                    else if (k < NH + ND) cv = emb[(size_t)tok * ND + k - NH];
                    else cv = douts_in[b * ND + k - NH - ND];
                    pp += Wpgen[NH + k] * cv;
                }
            }
            float ppt = blockReduceSum(pp, red);
            if (tid == 0) d_pgp[b * 4 + q4] = ppt;
        } else if (doV) {
            // P7a: combine S over 64 vocab blocks + write cols [vb*500, +250)
#pragma unroll
            for (int half2 = 0; half2 < 2; half2++) {
                int b = warp * 2 + half2;
                float s = 0.0f;
#pragma unroll
                for (int i = 0; i < 2; i++) s += d_ps6[(lane * 2 + i) * 16 + b];
                s = warpReduceSum(s);
                if (lane == 0) SM[SM_RED + b] = s;
            }
            __syncthreads();
            if (tid < 16)
                SM[SM_RED + 16 + tid] = __fdividef(d_pgen2[(tv & 1) * NB + tid],
                                                   SM[SM_RED + tid]);
            __syncthreads();
            if (tid < 250) {
                int vo = vb * 500 + tid;
                float r[NB];
#pragma unroll
                for (int b = 0; b < NB; b++)
                    r[b] = out_tv[(size_t)b * NVX + vo];
#pragma unroll
                for (int b = 0; b < NB; b++) {
                    float sm = SM[SM_RED + 16 + b] * SM[SM_LOGIT + b * 250 + tid];
                    out_tv[(size_t)b * NVX + vo] = flog(sm + r[b] + 1e-20f);
                }
            }
        }
        abarrier2(2, sub, 16);

        // ===== slot 4: chain P4 (pgen+scatter+tmp1) | vocab P7b =====
        if (doC) {
            if (bid < 16 && warp == 0) {
                float v = (lane < 4) ? d_pgp[bid * 4 + lane] : 0.0f;
                v = warpReduceSum(v);
                if (lane == 0) {
                    float pgv = sigf(v + bpgen[0]);
                    d_pgen2[(t & 1) * NB + bid] = pgv;
                    SM[12000] = 1.0f - pgv;
                }
            }
            int oo = tid & 127, q = tid >> 7;
            int oi = bid * 128 + oo;
            int b = oi >> 9, jj = oi & 511;
            int ks = q * 512;
            float acc = 0.0f;
#pragma unroll 4
            for (int k = ks; k < ks + 512; k++) {
                float iv = (k < NH) ? d_dh[pnxt + b * NH + k] : d_ctx[b * NH + k - NH];
                acc += iv * dWo1T[(size_t)k * NH + jj];
            }
            SM[q * 128 + oo] = acc;
            __syncthreads();   // also publishes SM[12000]
            if (tid < 128) {
                float s = SM[tid] + SM[128 + tid];
                int oi2 = bid * 128 + tid;
                d_tmp1[oi2] = ftanh(s + bo1v[oi2 & 511]);
            }
            if (bid < 16) {
                float omp = SM[12000];
                for (int s = tid; s < NS; s += 256) {
                    float val = omp * d_attn[bid * NS + s];
                    atomicAdd(out_t + (size_t)bid * NVX + srcext[bid * NS + s], val);
                }
            }
        } else if (doV) {
            // P7b: write cols [vb*500+250, +500) + NEX tail (vb<16)
            if (tid < 250) {
                int vo = vb * 500 + 250 + tid;
                float r[NB];
#pragma unroll
                for (int b = 0; b < NB; b++)
                    r[b] = out_tv[(size_t)b * NVX + vo];
#pragma unroll
                for (int b = 0; b < NB; b++) {
                    float sm = SM[SM_RED + 16 + b] * SM[SM_LOGIT + 4000 + b * 250 + tid];
                    out_tv[(size_t)b * NVX + vo] = flog(sm + r[b] + 1e-20f);
                }
            }
            if (vb < 16) {
                float* row = out_tv + (size_t)vb * NVX;
                for (int v = NV + tid; v < NVX; v += 256)
                    row[v] = flog(row[v] + 1e-20f);
            }
        }
        abarrier2(2, sub, 16);

        if (t == NT) break;   // epilogue (vocab for t=NT-1) done

        // ===== slot 5: chain P5 (dec_out) | vocab idle =====
        if (doC) {
            int oo = tid & 63, q = tid >> 6;
            int oi = bid * 64 + oo;
            int b = oi >> 8, jj = oi & 255;
            int ks = q * 128;
            float acc = 0.0f;
#pragma unroll 4
            for (int k = ks; k < ks + 128; k++)
                acc += d_tmp1[b * NH + k] * dWo2T[(size_t)k * ND + jj];
            SM[q * 64 + oo] = acc;
            __syncthreads();
            if (tid < 64) {
                float s = SM[tid] + SM[64 + tid] + SM[128 + tid] + SM[192 + tid];
                douts_out[bid * 64 + tid] = s;
            }
        }
        abarrier2(2, sub, 16);
    }
}

// ================================ host side ================================
extern "C" void kernel_launch(void* const* d_in, const int* in_sizes, int n_in,
                              void* d_out, int out_size) {
    const int* source   = (const int*)d_in[0];
    const int* srcext   = (const int*)d_in[1];
    const int* slen     = (const int*)d_in[2];
    const int* target   = (const int*)d_in[3];
    const float* emb    = (const float*)d_in[4];
    const float* eWih_f = (const float*)d_in[5];
    const float* eWhh_f = (const float*)d_in[6];
    const float* eb_f   = (const float*)d_in[7];
    const float* eWih_b = (const float*)d_in[8];
    const float* eWhh_b = (const float*)d_in[9];
    const float* eb_b   = (const float*)d_in[10];
    const float* Wproj  = (const float*)d_in[11];
    const float* bproj  = (const float*)d_in[12];
    const float* W2h    = (const float*)d_in[13];
    const float* b2h    = (const float*)d_in[14];
    const float* W2c    = (const float*)d_in[15];
    const float* b2c    = (const float*)d_in[16];
    const float* Wo1    = (const float*)d_in[17];
    const float* bo1    = (const float*)d_in[18];
    const float* Wo2    = (const float*)d_in[19];
    const float* dWih   = (const float*)d_in[20];
    const float* dWhh   = (const float*)d_in[21];
    const float* db     = (const float*)d_in[22];
    const float* Wpgen  = (const float*)d_in[23];
    const float* bpgen  = (const float*)d_in[24];
    float* out = (float*)d_out;

    dim3 tb(32, 8);
    k_setup_w<<<dim3(32, 64, 11), tb>>>(eWih_f, eWhh_f, eWih_b, eWhh_b,
                                        dWih, dWhh, Wproj, W2h, W2c, Wo1, Wo2);
    k_gx_emb<<<dim3(32, 250, 3), tb>>>(source, emb);
    k_encoder<<<NBLK, 256>>>(slen, eb_f, eb_b);
    k_megadec<<<NBLK, 256>>>(target, srcext, slen, emb, bproj, b2h, b2c,
                             db, bo1, Wpgen, bpgen, out);
}